// round 15
// baseline (speedup 1.0000x reference)
#include <cuda_runtime.h>
#include <cuda_fp16.h>
#include <cstdint>

// ---------------------------------------------------------------------------
// GCN_JK_Concat: 3x GCNConv(sym-norm, self-loops) + JK concat + Linear
// N=100000, E=1600000, F_IN=128, H=64, F_OUT=64
// R15 = R14 with the capture-fork bug fixed: side stream s2 waits on a root
// event recorded on the capture stream BEFORE its first kernel, so x2h/l1
// are captured into the graph (R14 ran them eagerly during capture, and
// k_scale_hw then re-scaled stale hw on every replay).
//   (a) k_x2h pre-converts x to fp16 on s2 (overlaps k_count)
//   (b) k_hmma_l1 reads fp16 x, no dis dependency (overlaps scan)
//   (c) k_scale_hw applies dis to hw (overlaps k_fill)
// Frozen: norm-factored CSR, int4-col gather, HMMA xform/cat, fused scan.
// ---------------------------------------------------------------------------

#define NMAX   100000
#define EMAX   1600000
#define NNZMAX (EMAX + NMAX)
#define NBSCAN 128

__device__ int     g_deg[NMAX];               // starts 0; reset by scan
__device__ float   g_dis[NMAX];
__device__ int     g_rowptr[NMAX + 1];
__device__ int     g_cursor[NMAX];
__device__ int     g_bsum[NBSCAN];
__device__ int     g_col[NNZMAX];             // col only (norm factored out)
__device__ __half2 g_xh[(size_t)NMAX * 64];   // fp16 copy of x
__device__ __half2 g_hw[(size_t)NMAX * 32];   // fp16 messages (dis-scaled)
__device__ __half2 g_h1[(size_t)NMAX * 32];
__device__ __half2 g_h2[(size_t)NMAX * 32];
__device__ __half2 g_h3[(size_t)NMAX * 32];
__device__ float   g_part[(size_t)NMAX * 64]; // x @ Wl[0:128] partial (fp32)

// ===========================================================================
// x -> fp16 conversion (streaming)
// ===========================================================================
__global__ void __launch_bounds__(256) k_x2h(const float* __restrict__ x, int n) {
    int i = blockIdx.x * blockDim.x + threadIdx.x;   // over n*32 uint2 stores
    if (i >= n * 32) return;
    float4 f = __ldg((const float4*)(x + (size_t)i * 4));
    uint2 q;
    __half2 h0 = __floats2half2_rn(f.x, f.y);
    __half2 h1 = __floats2half2_rn(f.z, f.w);
    q.x = *(uint32_t*)&h0;
    q.y = *(uint32_t*)&h1;
    *(uint2*)(g_xh + (size_t)i * 2) = q;
}

// hw *= dis[row]  (fp32 math)
__global__ void __launch_bounds__(256) k_scale_hw(int n) {
    int i = blockIdx.x * blockDim.x + threadIdx.x;   // over n*32 half2
    if (i >= n * 32) return;
    float d = g_dis[i >> 5];
    float2 f = __half22float2(g_hw[i]);
    g_hw[i] = __floats2half2_rn(f.x * d, f.y * d);
}

// ===========================================================================
// CSR build
// ===========================================================================
__global__ void k_count4(const int* __restrict__ ei, int e) {
    int i = blockIdx.x * blockDim.x + threadIdx.x;
    int base = 4 * i;
    if (base + 3 < e) {
        int4 d = *(const int4*)&ei[(size_t)e + base];
        atomicAdd(&g_deg[d.x], 1);
        atomicAdd(&g_deg[d.y], 1);
        atomicAdd(&g_deg[d.z], 1);
        atomicAdd(&g_deg[d.w], 1);
    } else {
        for (int j = base; j < e; j++)
            atomicAdd(&g_deg[ei[(size_t)e + j]], 1);
    }
}

__global__ void k_count1(const int* __restrict__ ei, int e) {
    int i = blockIdx.x * blockDim.x + threadIdx.x;
    if (i < e) atomicAdd(&g_deg[ei[(size_t)e + i]], 1);
}

__global__ void __launch_bounds__(1024) k_scan_local(int n) {
    __shared__ int warpsum[32];
    int t = threadIdx.x;
    int lane = t & 31;
    int w = t >> 5;
    int i = blockIdx.x * 1024 + t;
    int v = 0;
    if (i < n) {
        v = g_deg[i] + 1;        // +1 = self-loop
        g_deg[i] = 0;            // reset for next graph replay
    }
    int s = v;
    #pragma unroll
    for (int o = 1; o < 32; o <<= 1) {
        int x = __shfl_up_sync(0xffffffffu, s, o);
        if (lane >= o) s += x;
    }
    if (lane == 31) warpsum[w] = s;
    __syncthreads();
    if (w == 0) {
        int v2 = warpsum[lane];
        #pragma unroll
        for (int o = 1; o < 32; o <<= 1) {
            int x = __shfl_up_sync(0xffffffffu, v2, o);
            if (lane >= o) v2 += x;
        }
        warpsum[lane] = v2;
    }
    __syncthreads();
    int prefix = (w == 0) ? 0 : warpsum[w - 1];
    int incl = prefix + s;
    if (i < n) {
        g_rowptr[i] = incl - v;
        g_dis[i] = rsqrtf((float)v);
    }
    if (t == 1023) g_bsum[blockIdx.x] = incl;
}

__global__ void __launch_bounds__(1024) k_scan_add(int nb, int n) {
    __shared__ int s_off;
    int t = threadIdx.x;
    int bid = blockIdx.x;
    if (t < 32) {
        int acc = 0;
        for (int j = t; j < nb; j += 32)
            if (j < bid) acc += g_bsum[j];
        #pragma unroll
        for (int o = 16; o; o >>= 1) acc += __shfl_down_sync(0xffffffffu, acc, o);
        if (t == 0) s_off = acc;
    }
    __syncthreads();
    int off = s_off;
    int i = bid * 1024 + t;
    if (i < n) {
        int rp = g_rowptr[i] + off;
        g_rowptr[i] = rp;
        g_cursor[i] = rp;
    }
    if (bid == gridDim.x - 1 && t < 32) {
        int acc2 = 0;
        for (int j = t; j < nb; j += 32) acc2 += g_bsum[j];
        #pragma unroll
        for (int o = 16; o; o >>= 1) acc2 += __shfl_down_sync(0xffffffffu, acc2, o);
        if (t == 0) g_rowptr[n] = acc2;
    }
}

__global__ void k_fill(const int* __restrict__ ei, int e, int n) {
    int i = blockIdx.x * blockDim.x + threadIdx.x;
    int s, d;
    if (i < e) {
        s = ei[i];
        d = ei[(size_t)e + i];
    } else if (i < e + n) {
        s = d = i - e;                  // self-loop
    } else {
        return;
    }
    int pos = atomicAdd(&g_cursor[d], 1);
    g_col[pos] = s;
}

// ===========================================================================
// HMMA GEMM machinery
// ===========================================================================
#define PADH 72

__device__ __forceinline__ uint32_t smem_u32(const void* p) {
    return (uint32_t)__cvta_generic_to_shared(p);
}

#define LDSM_X4(r0, r1, r2, r3, addr) \
    asm volatile("ldmatrix.sync.aligned.m8n8.x4.shared.b16 {%0,%1,%2,%3}, [%4];" \
        : "=r"(r0), "=r"(r1), "=r"(r2), "=r"(r3) : "r"(addr))

#define LDSM_X4_T(r0, r1, r2, r3, addr) \
    asm volatile("ldmatrix.sync.aligned.m8n8.x4.trans.shared.b16 {%0,%1,%2,%3}, [%4];" \
        : "=r"(r0), "=r"(r1), "=r"(r2), "=r"(r3) : "r"(addr))

#define MMA16816(d, a, b0, b1) \
    asm volatile("mma.sync.aligned.m16n8k16.row.col.f32.f16.f16.f32 " \
        "{%0,%1,%2,%3}, {%4,%5,%6,%7}, {%8,%9}, {%0,%1,%2,%3};" \
        : "+f"((d)[0]), "+f"((d)[1]), "+f"((d)[2]), "+f"((d)[3]) \
        : "r"((a)[0]), "r"((a)[1]), "r"((a)[2]), "r"((a)[3]), "r"(b0), "r"(b1))

typedef __half ARow[PADH];

// fp16 A loader with arbitrary half2 row stride and half2 column offset
__device__ __forceinline__ void load_A16s(
    ARow* sA, const __half2* __restrict__ H, int strideH2, int koffH2,
    int rowBase, int n, int t)
{
    for (int idx = t; idx < 1024; idx += 128) {
        int row = idx >> 3, q = idx & 7;
        int gr = rowBase + row;
        uint4 v = make_uint4(0u, 0u, 0u, 0u);
        if (gr < n) v = *(const uint4*)&H[(size_t)gr * strideH2 + koffH2 + 4 * q];
        *(uint4*)&sA[row][8 * q] = v;
    }
}

__device__ __forceinline__ void load_Bg(
    ARow* sB, const float* __restrict__ W, int kk, int t)
{
    for (int idx = t; idx < 2048; idx += 128) {
        int k = idx >> 5, np = idx & 31;
        float2 f = *(const float2*)&W[(size_t)(kk + k) * 64 + 2 * np];
        *(__half2*)&sB[k][2 * np] = __float22half2_rn(f);
    }
}

__device__ __forceinline__ void hmma_tile_g(
    ARow* sA, ARow* sB, int warp, int lane, float acc[2][8][4])
{
    #pragma unroll
    for (int kc = 0; kc < 4; kc++) {
        int k0 = kc * 16;
        uint32_t a[2][4];
        #pragma unroll
        for (int m = 0; m < 2; m++) {
            uint32_t addr = smem_u32(
                &sA[warp * 32 + m * 16 + (lane & 15)][k0 + (lane >> 4) * 8]);
            LDSM_X4(a[m][0], a[m][1], a[m][2], a[m][3], addr);
        }
        #pragma unroll
        for (int jp = 0; jp < 4; jp++) {
            uint32_t b[4];
            uint32_t addr = smem_u32(
                &sB[k0 + (lane & 15)][jp * 16 + (lane >> 4) * 8]);
            LDSM_X4_T(b[0], b[1], b[2], b[3], addr);
            #pragma unroll
            for (int m = 0; m < 2; m++) {
                MMA16816(acc[m][2 * jp],     a[m], b[0], b[1]);
                MMA16816(acc[m][2 * jp + 1], a[m], b[2], b[3]);
            }
        }
    }
}

// Layer-1 fused GEMM (fp16 x): hw_raw = fp16(x@W0), g_part = fp32(x@Wl[0:128])
__global__ void __launch_bounds__(128) k_hmma_l1(
    const float* __restrict__ W0,
    const float* __restrict__ Wl,
    int n)
{
    __shared__ __half sA[128][PADH];
    __shared__ __half sBw[64][PADH];
    __shared__ __half sBl[64][PADH];
    int t = threadIdx.x;
    int lane = t & 31, warp = t >> 5;
    int rowBase = blockIdx.x * 128;
    float accW[2][8][4] = {};
    float accL[2][8][4] = {};

    for (int i = 0; i < 2; i++) {
        load_A16s(sA, g_xh, 64, i * 32, rowBase, n, t);
        load_Bg(sBw, W0, i * 64, t);
        load_Bg(sBl, Wl, i * 64, t);
        __syncthreads();
        hmma_tile_g(sA, sBw, warp, lane, accW);
        hmma_tile_g(sA, sBl, warp, lane, accL);
        __syncthreads();
    }

    int rw = rowBase + warp * 32;
    #pragma unroll
    for (int m = 0; m < 2; m++) {
        int r0 = rw + m * 16 + (lane >> 2);
        int r1 = r0 + 8;
        #pragma unroll
        for (int j = 0; j < 8; j++) {
            int col = 8 * j + 2 * (lane & 3);
            if (r0 < n) {
                g_hw[(size_t)r0 * 32 + (col >> 1)] =
                    __floats2half2_rn(accW[m][j][0], accW[m][j][1]);
                *(float2*)&g_part[(size_t)r0 * 64 + col] =
                    make_float2(accL[m][j][0], accL[m][j][1]);
            }
            if (r1 < n) {
                g_hw[(size_t)r1 * 32 + (col >> 1)] =
                    __floats2half2_rn(accW[m][j][2], accW[m][j][3]);
                *(float2*)&g_part[(size_t)r1 * 64 + col] =
                    make_float2(accL[m][j][2], accL[m][j][3]);
            }
        }
    }
}

// Layers 2,3 transform GEMM: out = fp16(dis .* (A16 @ W)), K=64
__global__ void __launch_bounds__(128) k_hmma_xform(
    const __half2* __restrict__ A16,
    const float* __restrict__ W,
    __half2* __restrict__ out, int n)
{
    __shared__ __half sA[128][PADH];
    __shared__ __half sB[64][PADH];
    int t = threadIdx.x;
    int lane = t & 31, warp = t >> 5;
    int rowBase = blockIdx.x * 128;
    float acc[2][8][4] = {};

    load_A16s(sA, A16, 32, 0, rowBase, n, t);
    load_Bg(sB, W, 0, t);
    __syncthreads();
    hmma_tile_g(sA, sB, warp, lane, acc);
    __syncthreads();

    int rw = rowBase + warp * 32;
    #pragma unroll
    for (int m = 0; m < 2; m++) {
        int r0 = rw + m * 16 + (lane >> 2);
        int r1 = r0 + 8;
        float d0 = (r0 < n) ? g_dis[r0] : 0.f;
        float d1 = (r1 < n) ? g_dis[r1] : 0.f;
        #pragma unroll
        for (int j = 0; j < 8; j++) {
            int col = 8 * j + 2 * (lane & 3);
            if (r0 < n)
                out[(size_t)r0 * 32 + (col >> 1)] =
                    __floats2half2_rn(acc[m][j][0] * d0, acc[m][j][1] * d0);
            if (r1 < n)
                out[(size_t)r1 * 32 + (col >> 1)] =
                    __floats2half2_rn(acc[m][j][2] * d1, acc[m][j][3] * d1);
        }
    }
}

// Final GEMM: out = partial + [h1|h2|h3] @ Wl[128:320] + bl   (K=192, fp16 A)
__global__ void __launch_bounds__(128) k_hmma_cat(
    const float* __restrict__ Wl,
    const float* __restrict__ bl,
    float* __restrict__ out, int n)
{
    __shared__ __half sA[128][PADH];
    __shared__ __half sB[64][PADH];
    int t = threadIdx.x;
    int lane = t & 31, warp = t >> 5;
    int rowBase = blockIdx.x * 128;
    float acc[2][8][4] = {};
    const float* Wl2 = Wl + 128 * 64;

    for (int i = 0; i < 3; i++) {
        const __half2* src = (i == 0) ? g_h1 : (i == 1) ? g_h2 : g_h3;
        load_A16s(sA, src, 32, 0, rowBase, n, t);
        load_Bg(sB, Wl2, i * 64, t);
        __syncthreads();
        hmma_tile_g(sA, sB, warp, lane, acc);
        __syncthreads();
    }

    int rw = rowBase + warp * 32;
    #pragma unroll
    for (int m = 0; m < 2; m++) {
        int r0 = rw + m * 16 + (lane >> 2);
        int r1 = r0 + 8;
        #pragma unroll
        for (int j = 0; j < 8; j++) {
            int col = 8 * j + 2 * (lane & 3);
            float b0 = bl[col], b1 = bl[col + 1];
            if (r0 < n) {
                float2 p = *(const float2*)&g_part[(size_t)r0 * 64 + col];
                *(float2*)&out[(size_t)r0 * 64 + col] =
                    make_float2(acc[m][j][0] + p.x + b0, acc[m][j][1] + p.y + b1);
            }
            if (r1 < n) {
                float2 p = *(const float2*)&g_part[(size_t)r1 * 64 + col];
                *(float2*)&out[(size_t)r1 * 64 + col] =
                    make_float2(acc[m][j][2] + p.x + b0, acc[m][j][3] + p.y + b1);
            }
        }
    }
}

// ===========================================================================
// Aggregation: warp per node, lane = one half2 (2 cols), unroll x8.
// Cols as int4 (2 LDG.128 per 8 edges); pure ADD inner op; dis[d] epilogue.
// ===========================================================================
__global__ void __launch_bounds__(256) k_gather(
    const __half2* __restrict__ hw,
    const float* __restrict__ bias,
    __half2* __restrict__ hout, int n)
{
    int g = blockIdx.x * blockDim.x + threadIdx.x;
    int node = g >> 5;
    int lane = g & 31;
    if (node >= n) return;
    int beg = g_rowptr[node];
    int end = g_rowptr[node + 1];
    float disd = g_dis[node];
    float a0 = 0.f, a1 = 0.f;
    int e = beg;
    while ((e & 3) && e < end) {
        int c = __ldg(&g_col[e]);
        float2 f = __half22float2(hw[(size_t)c * 32 + lane]);
        a0 += f.x; a1 += f.y;
        e++;
    }
    for (; e + 7 < end; e += 8) {
        int4 c0 = __ldg((const int4*)&g_col[e]);
        int4 c1 = __ldg((const int4*)&g_col[e + 4]);
        float2 f0 = __half22float2(hw[(size_t)c0.x * 32 + lane]);
        float2 f1 = __half22float2(hw[(size_t)c0.y * 32 + lane]);
        float2 f2 = __half22float2(hw[(size_t)c0.z * 32 + lane]);
        float2 f3 = __half22float2(hw[(size_t)c0.w * 32 + lane]);
        float2 f4 = __half22float2(hw[(size_t)c1.x * 32 + lane]);
        float2 f5 = __half22float2(hw[(size_t)c1.y * 32 + lane]);
        float2 f6 = __half22float2(hw[(size_t)c1.z * 32 + lane]);
        float2 f7 = __half22float2(hw[(size_t)c1.w * 32 + lane]);
        a0 += f0.x + f1.x + f2.x + f3.x;
        a1 += f0.y + f1.y + f2.y + f3.y;
        a0 += f4.x + f5.x + f6.x + f7.x;
        a1 += f4.y + f5.y + f6.y + f7.y;
    }
    for (; e < end; e++) {
        int c = __ldg(&g_col[e]);
        float2 f = __half22float2(hw[(size_t)c * 32 + lane]);
        a0 += f.x; a1 += f.y;
    }
    float b0 = bias[2 * lane], b1 = bias[2 * lane + 1];
    hout[(size_t)node * 32 + lane] =
        __floats2half2_rn(fmaxf(fmaf(disd, a0, b0), 0.f),
                          fmaxf(fmaf(disd, a1, b1), 0.f));
}

// ---------------------------------------------------------------------------
extern "C" void kernel_launch(void* const* d_in, const int* in_sizes, int n_in,
                              void* d_out, int out_size)
{
    const float* x  = (const float*)d_in[0];
    const int*   ei = (const int*)d_in[1];     // int32 edge_index [2, E]
    const float* W0 = (const float*)d_in[2];
    const float* b0 = (const float*)d_in[3];
    const float* W1 = (const float*)d_in[4];
    const float* b1 = (const float*)d_in[5];
    const float* W2 = (const float*)d_in[6];
    const float* b2 = (const float*)d_in[7];
    const float* Wl = (const float*)d_in[8];
    const float* bl = (const float*)d_in[9];
    float* out = (float*)d_out;

    int n = in_sizes[0] / 128;
    int e = in_sizes[1] / 2;
    int nb = (n + 1023) >> 10;

    __half2 *hw_ptr = nullptr, *h1_ptr = nullptr, *h2_ptr = nullptr, *h3_ptr = nullptr;
    cudaGetSymbolAddress((void**)&hw_ptr, g_hw);
    cudaGetSymbolAddress((void**)&h1_ptr, g_h1);
    cudaGetSymbolAddress((void**)&h2_ptr, g_h2);
    cudaGetSymbolAddress((void**)&h3_ptr, g_h3);

    int mma_blocks = (n + 127) / 128;
    int gather_blocks = (n * 32 + 255) / 256;
    int scale_blocks = (n * 32 + 255) / 256;

    cudaStream_t s2;
    cudaStreamCreate(&s2);
    cudaEvent_t evRoot, evScan, evL1;
    cudaEventCreateWithFlags(&evRoot, cudaEventDisableTiming);
    cudaEventCreateWithFlags(&evScan, cudaEventDisableTiming);
    cudaEventCreateWithFlags(&evL1, cudaEventDisableTiming);

    // ---- PROPER fork: s2 must acquire a capture dependency from the main
    // stream BEFORE its first kernel, or its work executes eagerly during
    // graph capture (the R14 bug).
    cudaEventRecord(evRoot, 0);
    cudaStreamWaitEvent(s2, evRoot, 0);

    // side stream: x->fp16 then layer-1 GEMM (no dis dependency)
    k_x2h<<<scale_blocks, 256, 0, s2>>>(x, n);
    k_hmma_l1<<<mma_blocks, 128, 0, s2>>>(W0, Wl, n);

    // ---- main stream: CSR build ----
    if ((e & 3) == 0) {
        int cth = e / 4;
        k_count4<<<(cth + 255) / 256, 256>>>(ei, e);
    } else {
        k_count1<<<(e + 255) / 256, 256>>>(ei, e);
    }
    k_scan_local<<<nb, 1024>>>(n);
    k_scan_add<<<nb, 1024>>>(nb, n);
    cudaEventRecord(evScan, 0);

    // scale hw by dis on s2 (after l1 in stream order; needs scan)
    cudaStreamWaitEvent(s2, evScan, 0);
    k_scale_hw<<<scale_blocks, 256, 0, s2>>>(n);
    cudaEventRecord(evL1, s2);

    k_fill<<<(e + n + 255) / 256, 256>>>(ei, e, n);

    // join: gather needs CSR fill + scaled hw
    cudaStreamWaitEvent(0, evL1, 0);

    // ---- layer 1 aggregate ----
    k_gather<<<gather_blocks, 256>>>(hw_ptr, b0, h1_ptr, n);
    // ---- layer 2 ----
    k_hmma_xform<<<mma_blocks, 128>>>(h1_ptr, W1, hw_ptr, n);
    k_gather<<<gather_blocks, 256>>>(hw_ptr, b1, h2_ptr, n);
    // ---- layer 3 ----
    k_hmma_xform<<<mma_blocks, 128>>>(h2_ptr, W2, hw_ptr, n);
    k_gather<<<gather_blocks, 256>>>(hw_ptr, b2, h3_ptr, n);
    // ---- JK concat + linear (K=192 fp16 + partial) ----
    k_hmma_cat<<<mma_blocks, 128>>>(Wl, bl, out, n);

    cudaEventDestroy(evRoot);
    cudaEventDestroy(evScan);
    cudaEventDestroy(evL1);
    cudaStreamDestroy(s2);
}

// round 16
// speedup vs baseline: 1.0627x; 1.0627x over previous
#include <cuda_runtime.h>
#include <cuda_fp16.h>
#include <cstdint>

// ---------------------------------------------------------------------------
// GCN_JK_Concat: 3x GCNConv(sym-norm, self-loops) + JK concat + Linear
// N=100000, E=1600000, F_IN=128, H=64, F_OUT=64
// R16 = R13 (best, 264.4us) with all HMMA GEMM kernels widened to 256 threads
// (8 warps, one 16-row m-tile per warp): halves per-thread accumulators,
// raises occupancy of the latency-bound k_hmma_l1 (was 166 regs, occ 16%).
// Frozen from R13: norm-factored col-only CSR, int4-col gather, fused scan,
// scan->l1 side-stream fork, x@Wl partial fusion.
// ---------------------------------------------------------------------------

#define NMAX   100000
#define EMAX   1600000
#define NNZMAX (EMAX + NMAX)
#define NBSCAN 128

__device__ int     g_deg[NMAX];               // starts 0; reset by scan
__device__ float   g_dis[NMAX];
__device__ int     g_rowptr[NMAX + 1];
__device__ int     g_cursor[NMAX];
__device__ int     g_bsum[NBSCAN];
__device__ int     g_col[NNZMAX];             // col only (norm factored out)
__device__ __half2 g_hw[(size_t)NMAX * 32];   // dis-scaled fp16 messages
__device__ __half2 g_h1[(size_t)NMAX * 32];
__device__ __half2 g_h2[(size_t)NMAX * 32];
__device__ __half2 g_h3[(size_t)NMAX * 32];
__device__ float   g_part[(size_t)NMAX * 64]; // x @ Wl[0:128] partial (fp32)

// ===========================================================================
// CSR build
// ===========================================================================
__global__ void k_count4(const int* __restrict__ ei, int e) {
    int i = blockIdx.x * blockDim.x + threadIdx.x;
    int base = 4 * i;
    if (base + 3 < e) {
        int4 d = *(const int4*)&ei[(size_t)e + base];
        atomicAdd(&g_deg[d.x], 1);
        atomicAdd(&g_deg[d.y], 1);
        atomicAdd(&g_deg[d.z], 1);
        atomicAdd(&g_deg[d.w], 1);
    } else {
        for (int j = base; j < e; j++)
            atomicAdd(&g_deg[ei[(size_t)e + j]], 1);
    }
}

__global__ void k_count1(const int* __restrict__ ei, int e) {
    int i = blockIdx.x * blockDim.x + threadIdx.x;
    if (i < e) atomicAdd(&g_deg[ei[(size_t)e + i]], 1);
}

__global__ void __launch_bounds__(1024) k_scan_local(int n) {
    __shared__ int warpsum[32];
    int t = threadIdx.x;
    int lane = t & 31;
    int w = t >> 5;
    int i = blockIdx.x * 1024 + t;
    int v = 0;
    if (i < n) {
        v = g_deg[i] + 1;        // +1 = self-loop
        g_deg[i] = 0;            // reset for next graph replay
    }
    int s = v;
    #pragma unroll
    for (int o = 1; o < 32; o <<= 1) {
        int x = __shfl_up_sync(0xffffffffu, s, o);
        if (lane >= o) s += x;
    }
    if (lane == 31) warpsum[w] = s;
    __syncthreads();
    if (w == 0) {
        int v2 = warpsum[lane];
        #pragma unroll
        for (int o = 1; o < 32; o <<= 1) {
            int x = __shfl_up_sync(0xffffffffu, v2, o);
            if (lane >= o) v2 += x;
        }
        warpsum[lane] = v2;
    }
    __syncthreads();
    int prefix = (w == 0) ? 0 : warpsum[w - 1];
    int incl = prefix + s;
    if (i < n) {
        g_rowptr[i] = incl - v;
        g_dis[i] = rsqrtf((float)v);
    }
    if (t == 1023) g_bsum[blockIdx.x] = incl;
}

__global__ void __launch_bounds__(1024) k_scan_add(int nb, int n) {
    __shared__ int s_off;
    int t = threadIdx.x;
    int bid = blockIdx.x;
    if (t < 32) {
        int acc = 0;
        for (int j = t; j < nb; j += 32)
            if (j < bid) acc += g_bsum[j];
        #pragma unroll
        for (int o = 16; o; o >>= 1) acc += __shfl_down_sync(0xffffffffu, acc, o);
        if (t == 0) s_off = acc;
    }
    __syncthreads();
    int off = s_off;
    int i = bid * 1024 + t;
    if (i < n) {
        int rp = g_rowptr[i] + off;
        g_rowptr[i] = rp;
        g_cursor[i] = rp;
    }
    if (bid == gridDim.x - 1 && t < 32) {
        int acc2 = 0;
        for (int j = t; j < nb; j += 32) acc2 += g_bsum[j];
        #pragma unroll
        for (int o = 16; o; o >>= 1) acc2 += __shfl_down_sync(0xffffffffu, acc2, o);
        if (t == 0) g_rowptr[n] = acc2;
    }
}

__global__ void k_fill(const int* __restrict__ ei, int e, int n) {
    int i = blockIdx.x * blockDim.x + threadIdx.x;
    int s, d;
    if (i < e) {
        s = ei[i];
        d = ei[(size_t)e + i];
    } else if (i < e + n) {
        s = d = i - e;                  // self-loop
    } else {
        return;
    }
    int pos = atomicAdd(&g_cursor[d], 1);
    g_col[pos] = s;
}

// ===========================================================================
// HMMA GEMM machinery -- 256 threads / 8 warps per 128-row tile
// ===========================================================================
#define PADH 72
#define GNT 256   // GEMM block threads

__device__ __forceinline__ uint32_t smem_u32(const void* p) {
    return (uint32_t)__cvta_generic_to_shared(p);
}

#define LDSM_X4(r0, r1, r2, r3, addr) \
    asm volatile("ldmatrix.sync.aligned.m8n8.x4.shared.b16 {%0,%1,%2,%3}, [%4];" \
        : "=r"(r0), "=r"(r1), "=r"(r2), "=r"(r3) : "r"(addr))

#define LDSM_X4_T(r0, r1, r2, r3, addr) \
    asm volatile("ldmatrix.sync.aligned.m8n8.x4.trans.shared.b16 {%0,%1,%2,%3}, [%4];" \
        : "=r"(r0), "=r"(r1), "=r"(r2), "=r"(r3) : "r"(addr))

#define MMA16816(d, a, b0, b1) \
    asm volatile("mma.sync.aligned.m16n8k16.row.col.f32.f16.f16.f32 " \
        "{%0,%1,%2,%3}, {%4,%5,%6,%7}, {%8,%9}, {%0,%1,%2,%3};" \
        : "+f"((d)[0]), "+f"((d)[1]), "+f"((d)[2]), "+f"((d)[3]) \
        : "r"((a)[0]), "r"((a)[1]), "r"((a)[2]), "r"((a)[3]), "r"(b0), "r"(b1))

typedef __half ARow[PADH];

__device__ __forceinline__ void load_A32g(
    ARow* sA, const float* __restrict__ A, int K, int kk,
    int rowBase, int n, int t)
{
    for (int idx = t; idx < 4096; idx += GNT) {
        int row = idx >> 5, kp = idx & 31;
        int gr = rowBase + row;
        float2 f = make_float2(0.f, 0.f);
        if (gr < n) f = *(const float2*)&A[(size_t)gr * K + kk + 2 * kp];
        *(__half2*)&sA[row][2 * kp] = __float22half2_rn(f);
    }
}

__device__ __forceinline__ void load_A16g(
    ARow* sA, const __half2* __restrict__ H, int rowBase, int n, int t)
{
    for (int idx = t; idx < 1024; idx += GNT) {
        int row = idx >> 3, q = idx & 7;
        int gr = rowBase + row;
        uint4 v = make_uint4(0u, 0u, 0u, 0u);
        if (gr < n) v = *(const uint4*)&H[(size_t)gr * 32 + 4 * q];
        *(uint4*)&sA[row][8 * q] = v;
    }
}

__device__ __forceinline__ void load_Bg(
    ARow* sB, const float* __restrict__ W, int kk, int t)
{
    for (int idx = t; idx < 2048; idx += GNT) {
        int k = idx >> 5, np = idx & 31;
        float2 f = *(const float2*)&W[(size_t)(kk + k) * 64 + 2 * np];
        *(__half2*)&sB[k][2 * np] = __float22half2_rn(f);
    }
}

// one 16-row m-tile per warp (8 warps cover 128 rows)
__device__ __forceinline__ void hmma_tile8(
    ARow* sA, ARow* sB, int warp, int lane, float acc[8][4])
{
    #pragma unroll
    for (int kc = 0; kc < 4; kc++) {
        int k0 = kc * 16;
        uint32_t a[4];
        uint32_t aaddr = smem_u32(
            &sA[warp * 16 + (lane & 15)][k0 + (lane >> 4) * 8]);
        LDSM_X4(a[0], a[1], a[2], a[3], aaddr);
        #pragma unroll
        for (int jp = 0; jp < 4; jp++) {
            uint32_t b[4];
            uint32_t baddr = smem_u32(
                &sB[k0 + (lane & 15)][jp * 16 + (lane >> 4) * 8]);
            LDSM_X4_T(b[0], b[1], b[2], b[3], baddr);
            MMA16816(acc[2 * jp],     a, b[0], b[1]);
            MMA16816(acc[2 * jp + 1], a, b[2], b[3]);
        }
    }
}

// Layer-1 fused GEMM: hw = fp16(dis .* (x@W0)), g_part = fp32(x@Wl[0:128])
__global__ void __launch_bounds__(GNT) k_hmma_l1(
    const float* __restrict__ x,
    const float* __restrict__ W0,
    const float* __restrict__ Wl,
    __half2* __restrict__ out, int n)
{
    __shared__ __half sA[128][PADH];
    __shared__ __half sBw[64][PADH];
    __shared__ __half sBl[64][PADH];
    int t = threadIdx.x;
    int lane = t & 31, warp = t >> 5;
    int rowBase = blockIdx.x * 128;
    float accW[8][4] = {};
    float accL[8][4] = {};

    for (int i = 0; i < 2; i++) {
        load_A32g(sA, x, 128, i * 64, rowBase, n, t);
        load_Bg(sBw, W0, i * 64, t);
        load_Bg(sBl, Wl, i * 64, t);
        __syncthreads();
        hmma_tile8(sA, sBw, warp, lane, accW);
        hmma_tile8(sA, sBl, warp, lane, accL);
        __syncthreads();
    }

    int r0 = rowBase + warp * 16 + (lane >> 2);
    int r1 = r0 + 8;
    float d0 = (r0 < n) ? g_dis[r0] : 0.f;
    float d1 = (r1 < n) ? g_dis[r1] : 0.f;
    #pragma unroll
    for (int j = 0; j < 8; j++) {
        int col = 8 * j + 2 * (lane & 3);
        if (r0 < n) {
            out[(size_t)r0 * 32 + (col >> 1)] =
                __floats2half2_rn(accW[j][0] * d0, accW[j][1] * d0);
            *(float2*)&g_part[(size_t)r0 * 64 + col] =
                make_float2(accL[j][0], accL[j][1]);
        }
        if (r1 < n) {
            out[(size_t)r1 * 32 + (col >> 1)] =
                __floats2half2_rn(accW[j][2] * d1, accW[j][3] * d1);
            *(float2*)&g_part[(size_t)r1 * 64 + col] =
                make_float2(accL[j][2], accL[j][3]);
        }
    }
}

// Layers 2,3 transform GEMM: out = fp16(dis .* (A16 @ W)), K=64
__global__ void __launch_bounds__(GNT) k_hmma_xform(
    const __half2* __restrict__ A16,
    const float* __restrict__ W,
    __half2* __restrict__ out, int n)
{
    __shared__ __half sA[128][PADH];
    __shared__ __half sB[64][PADH];
    int t = threadIdx.x;
    int lane = t & 31, warp = t >> 5;
    int rowBase = blockIdx.x * 128;
    float acc[8][4] = {};

    load_A16g(sA, A16, rowBase, n, t);
    load_Bg(sB, W, 0, t);
    __syncthreads();
    hmma_tile8(sA, sB, warp, lane, acc);
    __syncthreads();

    int r0 = rowBase + warp * 16 + (lane >> 2);
    int r1 = r0 + 8;
    float d0 = (r0 < n) ? g_dis[r0] : 0.f;
    float d1 = (r1 < n) ? g_dis[r1] : 0.f;
    #pragma unroll
    for (int j = 0; j < 8; j++) {
        int col = 8 * j + 2 * (lane & 3);
        if (r0 < n)
            out[(size_t)r0 * 32 + (col >> 1)] =
                __floats2half2_rn(acc[j][0] * d0, acc[j][1] * d0);
        if (r1 < n)
            out[(size_t)r1 * 32 + (col >> 1)] =
                __floats2half2_rn(acc[j][2] * d1, acc[j][3] * d1);
    }
}

// Final GEMM: out = partial + [h1|h2|h3] @ Wl[128:320] + bl   (K=192, fp16 A)
__global__ void __launch_bounds__(GNT) k_hmma_cat(
    const float* __restrict__ Wl,
    const float* __restrict__ bl,
    float* __restrict__ out, int n)
{
    __shared__ __half sA[128][PADH];
    __shared__ __half sB[64][PADH];
    int t = threadIdx.x;
    int lane = t & 31, warp = t >> 5;
    int rowBase = blockIdx.x * 128;
    float acc[8][4] = {};
    const float* Wl2 = Wl + 128 * 64;

    for (int i = 0; i < 3; i++) {
        const __half2* src = (i == 0) ? g_h1 : (i == 1) ? g_h2 : g_h3;
        load_A16g(sA, src, rowBase, n, t);
        load_Bg(sB, Wl2, i * 64, t);
        __syncthreads();
        hmma_tile8(sA, sB, warp, lane, acc);
        __syncthreads();
    }

    int r0 = rowBase + warp * 16 + (lane >> 2);
    int r1 = r0 + 8;
    #pragma unroll
    for (int j = 0; j < 8; j++) {
        int col = 8 * j + 2 * (lane & 3);
        float b0 = bl[col], b1 = bl[col + 1];
        if (r0 < n) {
            float2 p = *(const float2*)&g_part[(size_t)r0 * 64 + col];
            *(float2*)&out[(size_t)r0 * 64 + col] =
                make_float2(acc[j][0] + p.x + b0, acc[j][1] + p.y + b1);
        }
        if (r1 < n) {
            float2 p = *(const float2*)&g_part[(size_t)r1 * 64 + col];
            *(float2*)&out[(size_t)r1 * 64 + col] =
                make_float2(acc[j][2] + p.x + b0, acc[j][3] + p.y + b1);
        }
    }
}

// ===========================================================================
// Aggregation: warp per node, lane = one half2 (2 cols), unroll x8.
// Cols as int4 (2 LDG.128 per 8 edges); pure ADD inner op; dis[d] epilogue.
// ===========================================================================
__global__ void __launch_bounds__(256) k_gather(
    const __half2* __restrict__ hw,
    const float* __restrict__ bias,
    __half2* __restrict__ hout, int n)
{
    int g = blockIdx.x * blockDim.x + threadIdx.x;
    int node = g >> 5;
    int lane = g & 31;
    if (node >= n) return;
    int beg = g_rowptr[node];
    int end = g_rowptr[node + 1];
    float disd = g_dis[node];
    float a0 = 0.f, a1 = 0.f;
    int e = beg;
    while ((e & 3) && e < end) {
        int c = __ldg(&g_col[e]);
        float2 f = __half22float2(hw[(size_t)c * 32 + lane]);
        a0 += f.x; a1 += f.y;
        e++;
    }
    for (; e + 7 < end; e += 8) {
        int4 c0 = __ldg((const int4*)&g_col[e]);
        int4 c1 = __ldg((const int4*)&g_col[e + 4]);
        float2 f0 = __half22float2(hw[(size_t)c0.x * 32 + lane]);
        float2 f1 = __half22float2(hw[(size_t)c0.y * 32 + lane]);
        float2 f2 = __half22float2(hw[(size_t)c0.z * 32 + lane]);
        float2 f3 = __half22float2(hw[(size_t)c0.w * 32 + lane]);
        float2 f4 = __half22float2(hw[(size_t)c1.x * 32 + lane]);
        float2 f5 = __half22float2(hw[(size_t)c1.y * 32 + lane]);
        float2 f6 = __half22float2(hw[(size_t)c1.z * 32 + lane]);
        float2 f7 = __half22float2(hw[(size_t)c1.w * 32 + lane]);
        a0 += f0.x + f1.x + f2.x + f3.x;
        a1 += f0.y + f1.y + f2.y + f3.y;
        a0 += f4.x + f5.x + f6.x + f7.x;
        a1 += f4.y + f5.y + f6.y + f7.y;
    }
    for (; e < end; e++) {
        int c = __ldg(&g_col[e]);
        float2 f = __half22float2(hw[(size_t)c * 32 + lane]);
        a0 += f.x; a1 += f.y;
    }
    float b0 = bias[2 * lane], b1 = bias[2 * lane + 1];
    hout[(size_t)node * 32 + lane] =
        __floats2half2_rn(fmaxf(fmaf(disd, a0, b0), 0.f),
                          fmaxf(fmaf(disd, a1, b1), 0.f));
}

// ---------------------------------------------------------------------------
extern "C" void kernel_launch(void* const* d_in, const int* in_sizes, int n_in,
                              void* d_out, int out_size)
{
    const float* x  = (const float*)d_in[0];
    const int*   ei = (const int*)d_in[1];     // int32 edge_index [2, E]
    const float* W0 = (const float*)d_in[2];
    const float* b0 = (const float*)d_in[3];
    const float* W1 = (const float*)d_in[4];
    const float* b1 = (const float*)d_in[5];
    const float* W2 = (const float*)d_in[6];
    const float* b2 = (const float*)d_in[7];
    const float* Wl = (const float*)d_in[8];
    const float* bl = (const float*)d_in[9];
    float* out = (float*)d_out;

    int n = in_sizes[0] / 128;
    int e = in_sizes[1] / 2;
    int nb = (n + 1023) >> 10;

    __half2 *hw_ptr = nullptr, *h1_ptr = nullptr, *h2_ptr = nullptr, *h3_ptr = nullptr;
    cudaGetSymbolAddress((void**)&hw_ptr, g_hw);
    cudaGetSymbolAddress((void**)&h1_ptr, g_h1);
    cudaGetSymbolAddress((void**)&h2_ptr, g_h2);
    cudaGetSymbolAddress((void**)&h3_ptr, g_h3);

    int mma_blocks = (n + 127) / 128;
    int gather_blocks = (n * 32 + 255) / 256;

    cudaStream_t s2;
    cudaStreamCreate(&s2);
    cudaEvent_t evScan, evL1;
    cudaEventCreateWithFlags(&evScan, cudaEventDisableTiming);
    cudaEventCreateWithFlags(&evL1, cudaEventDisableTiming);

    // ---- CSR build (main stream) ----
    if ((e & 3) == 0) {
        int cth = e / 4;
        k_count4<<<(cth + 255) / 256, 256>>>(ei, e);
    } else {
        k_count1<<<(e + 255) / 256, 256>>>(ei, e);
    }
    k_scan_local<<<nb, 1024>>>(n);
    k_scan_add<<<nb, 1024>>>(nb, n);
    cudaEventRecord(evScan, 0);

    // layer-1 GEMM on side stream (needs dis; overlaps with k_fill)
    cudaStreamWaitEvent(s2, evScan, 0);
    k_hmma_l1<<<mma_blocks, GNT, 0, s2>>>(x, W0, Wl, hw_ptr, n);
    cudaEventRecord(evL1, s2);

    k_fill<<<(e + n + 255) / 256, 256>>>(ei, e, n);

    // join: gather needs both CSR fill and hw
    cudaStreamWaitEvent(0, evL1, 0);

    // ---- layer 1 aggregate ----
    k_gather<<<gather_blocks, 256>>>(hw_ptr, b0, h1_ptr, n);
    // ---- layer 2 ----
    k_hmma_xform<<<mma_blocks, GNT>>>(h1_ptr, W1, hw_ptr, n);
    k_gather<<<gather_blocks, 256>>>(hw_ptr, b1, h2_ptr, n);
    // ---- layer 3 ----
    k_hmma_xform<<<mma_blocks, GNT>>>(h2_ptr, W2, hw_ptr, n);
    k_gather<<<gather_blocks, 256>>>(hw_ptr, b2, h3_ptr, n);
    // ---- JK concat + linear (K=192 fp16 + partial) ----
    k_hmma_cat<<<mma_blocks, GNT>>>(Wl, bl, out, n);

    cudaEventDestroy(evScan);
    cudaEventDestroy(evL1);
    cudaStreamDestroy(s2);
}

// round 17
// speedup vs baseline: 1.0806x; 1.0169x over previous
#include <cuda_runtime.h>
#include <cuda_fp16.h>
#include <cstdint>

// ---------------------------------------------------------------------------
// GCN_JK_Concat: 3x GCNConv(sym-norm, self-loops) + JK concat + Linear
// N=100000, E=1600000, F_IN=128, H=64, F_OUT=64
// R17 = R16 with k_hmma_l1 split by dependency:
//   k_hmma_part (x@Wl[0:128] -> g_part): NO dependencies, starts at t=0 on
//     s3, joined only before the final cat GEMM -- off the critical path.
//   k_hmma_w0 (x@W0 -> hw, dis epilogue): on s2 after scan, overlaps fill.
// Frozen: 256-thread HMMA tiles (R16), norm-factored col-only CSR,
// int4-col gather, fused scan.
// ---------------------------------------------------------------------------

#define NMAX   100000
#define EMAX   1600000
#define NNZMAX (EMAX + NMAX)
#define NBSCAN 128

__device__ int     g_deg[NMAX];               // starts 0; reset by scan
__device__ float   g_dis[NMAX];
__device__ int     g_rowptr[NMAX + 1];
__device__ int     g_cursor[NMAX];
__device__ int     g_bsum[NBSCAN];
__device__ int     g_col[NNZMAX];             // col only (norm factored out)
__device__ __half2 g_hw[(size_t)NMAX * 32];   // dis-scaled fp16 messages
__device__ __half2 g_h1[(size_t)NMAX * 32];
__device__ __half2 g_h2[(size_t)NMAX * 32];
__device__ __half2 g_h3[(size_t)NMAX * 32];
__device__ float   g_part[(size_t)NMAX * 64]; // x @ Wl[0:128] partial (fp32)

// ===========================================================================
// CSR build
// ===========================================================================
__global__ void k_count4(const int* __restrict__ ei, int e) {
    int i = blockIdx.x * blockDim.x + threadIdx.x;
    int base = 4 * i;
    if (base + 3 < e) {
        int4 d = *(const int4*)&ei[(size_t)e + base];
        atomicAdd(&g_deg[d.x], 1);
        atomicAdd(&g_deg[d.y], 1);
        atomicAdd(&g_deg[d.z], 1);
        atomicAdd(&g_deg[d.w], 1);
    } else {
        for (int j = base; j < e; j++)
            atomicAdd(&g_deg[ei[(size_t)e + j]], 1);
    }
}

__global__ void k_count1(const int* __restrict__ ei, int e) {
    int i = blockIdx.x * blockDim.x + threadIdx.x;
    if (i < e) atomicAdd(&g_deg[ei[(size_t)e + i]], 1);
}

__global__ void __launch_bounds__(1024) k_scan_local(int n) {
    __shared__ int warpsum[32];
    int t = threadIdx.x;
    int lane = t & 31;
    int w = t >> 5;
    int i = blockIdx.x * 1024 + t;
    int v = 0;
    if (i < n) {
        v = g_deg[i] + 1;        // +1 = self-loop
        g_deg[i] = 0;            // reset for next graph replay
    }
    int s = v;
    #pragma unroll
    for (int o = 1; o < 32; o <<= 1) {
        int x = __shfl_up_sync(0xffffffffu, s, o);
        if (lane >= o) s += x;
    }
    if (lane == 31) warpsum[w] = s;
    __syncthreads();
    if (w == 0) {
        int v2 = warpsum[lane];
        #pragma unroll
        for (int o = 1; o < 32; o <<= 1) {
            int x = __shfl_up_sync(0xffffffffu, v2, o);
            if (lane >= o) v2 += x;
        }
        warpsum[lane] = v2;
    }
    __syncthreads();
    int prefix = (w == 0) ? 0 : warpsum[w - 1];
    int incl = prefix + s;
    if (i < n) {
        g_rowptr[i] = incl - v;
        g_dis[i] = rsqrtf((float)v);
    }
    if (t == 1023) g_bsum[blockIdx.x] = incl;
}

__global__ void __launch_bounds__(1024) k_scan_add(int nb, int n) {
    __shared__ int s_off;
    int t = threadIdx.x;
    int bid = blockIdx.x;
    if (t < 32) {
        int acc = 0;
        for (int j = t; j < nb; j += 32)
            if (j < bid) acc += g_bsum[j];
        #pragma unroll
        for (int o = 16; o; o >>= 1) acc += __shfl_down_sync(0xffffffffu, acc, o);
        if (t == 0) s_off = acc;
    }
    __syncthreads();
    int off = s_off;
    int i = bid * 1024 + t;
    if (i < n) {
        int rp = g_rowptr[i] + off;
        g_rowptr[i] = rp;
        g_cursor[i] = rp;
    }
    if (bid == gridDim.x - 1 && t < 32) {
        int acc2 = 0;
        for (int j = t; j < nb; j += 32) acc2 += g_bsum[j];
        #pragma unroll
        for (int o = 16; o; o >>= 1) acc2 += __shfl_down_sync(0xffffffffu, acc2, o);
        if (t == 0) g_rowptr[n] = acc2;
    }
}

__global__ void k_fill(const int* __restrict__ ei, int e, int n) {
    int i = blockIdx.x * blockDim.x + threadIdx.x;
    int s, d;
    if (i < e) {
        s = ei[i];
        d = ei[(size_t)e + i];
    } else if (i < e + n) {
        s = d = i - e;                  // self-loop
    } else {
        return;
    }
    int pos = atomicAdd(&g_cursor[d], 1);
    g_col[pos] = s;
}

// ===========================================================================
// HMMA GEMM machinery -- 256 threads / 8 warps per 128-row tile
// ===========================================================================
#define PADH 72
#define GNT 256

__device__ __forceinline__ uint32_t smem_u32(const void* p) {
    return (uint32_t)__cvta_generic_to_shared(p);
}

#define LDSM_X4(r0, r1, r2, r3, addr) \
    asm volatile("ldmatrix.sync.aligned.m8n8.x4.shared.b16 {%0,%1,%2,%3}, [%4];" \
        : "=r"(r0), "=r"(r1), "=r"(r2), "=r"(r3) : "r"(addr))

#define LDSM_X4_T(r0, r1, r2, r3, addr) \
    asm volatile("ldmatrix.sync.aligned.m8n8.x4.trans.shared.b16 {%0,%1,%2,%3}, [%4];" \
        : "=r"(r0), "=r"(r1), "=r"(r2), "=r"(r3) : "r"(addr))

#define MMA16816(d, a, b0, b1) \
    asm volatile("mma.sync.aligned.m16n8k16.row.col.f32.f16.f16.f32 " \
        "{%0,%1,%2,%3}, {%4,%5,%6,%7}, {%8,%9}, {%0,%1,%2,%3};" \
        : "+f"((d)[0]), "+f"((d)[1]), "+f"((d)[2]), "+f"((d)[3]) \
        : "r"((a)[0]), "r"((a)[1]), "r"((a)[2]), "r"((a)[3]), "r"(b0), "r"(b1))

typedef __half ARow[PADH];

__device__ __forceinline__ void load_A32g(
    ARow* sA, const float* __restrict__ A, int K, int kk,
    int rowBase, int n, int t)
{
    for (int idx = t; idx < 4096; idx += GNT) {
        int row = idx >> 5, kp = idx & 31;
        int gr = rowBase + row;
        float2 f = make_float2(0.f, 0.f);
        if (gr < n) f = *(const float2*)&A[(size_t)gr * K + kk + 2 * kp];
        *(__half2*)&sA[row][2 * kp] = __float22half2_rn(f);
    }
}

__device__ __forceinline__ void load_A16g(
    ARow* sA, const __half2* __restrict__ H, int rowBase, int n, int t)
{
    for (int idx = t; idx < 1024; idx += GNT) {
        int row = idx >> 3, q = idx & 7;
        int gr = rowBase + row;
        uint4 v = make_uint4(0u, 0u, 0u, 0u);
        if (gr < n) v = *(const uint4*)&H[(size_t)gr * 32 + 4 * q];
        *(uint4*)&sA[row][8 * q] = v;
    }
}

__device__ __forceinline__ void load_Bg(
    ARow* sB, const float* __restrict__ W, int kk, int t)
{
    for (int idx = t; idx < 2048; idx += GNT) {
        int k = idx >> 5, np = idx & 31;
        float2 f = *(const float2*)&W[(size_t)(kk + k) * 64 + 2 * np];
        *(__half2*)&sB[k][2 * np] = __float22half2_rn(f);
    }
}

// one 16-row m-tile per warp (8 warps cover 128 rows)
__device__ __forceinline__ void hmma_tile8(
    ARow* sA, ARow* sB, int warp, int lane, float acc[8][4])
{
    #pragma unroll
    for (int kc = 0; kc < 4; kc++) {
        int k0 = kc * 16;
        uint32_t a[4];
        uint32_t aaddr = smem_u32(
            &sA[warp * 16 + (lane & 15)][k0 + (lane >> 4) * 8]);
        LDSM_X4(a[0], a[1], a[2], a[3], aaddr);
        #pragma unroll
        for (int jp = 0; jp < 4; jp++) {
            uint32_t b[4];
            uint32_t baddr = smem_u32(
                &sB[k0 + (lane & 15)][jp * 16 + (lane >> 4) * 8]);
            LDSM_X4_T(b[0], b[1], b[2], b[3], baddr);
            MMA16816(acc[2 * jp],     a, b[0], b[1]);
            MMA16816(acc[2 * jp + 1], a, b[2], b[3]);
        }
    }
}

// x @ Wl[0:128] -> g_part (fp32). No dependencies; runs at t=0.
__global__ void __launch_bounds__(GNT) k_hmma_part(
    const float* __restrict__ x,
    const float* __restrict__ Wl,
    int n)
{
    __shared__ __half sA[128][PADH];
    __shared__ __half sB[64][PADH];
    int t = threadIdx.x;
    int lane = t & 31, warp = t >> 5;
    int rowBase = blockIdx.x * 128;
    float acc[8][4] = {};

    for (int i = 0; i < 2; i++) {
        load_A32g(sA, x, 128, i * 64, rowBase, n, t);
        load_Bg(sB, Wl, i * 64, t);
        __syncthreads();
        hmma_tile8(sA, sB, warp, lane, acc);
        __syncthreads();
    }

    int r0 = rowBase + warp * 16 + (lane >> 2);
    int r1 = r0 + 8;
    #pragma unroll
    for (int j = 0; j < 8; j++) {
        int col = 8 * j + 2 * (lane & 3);
        if (r0 < n)
            *(float2*)&g_part[(size_t)r0 * 64 + col] =
                make_float2(acc[j][0], acc[j][1]);
        if (r1 < n)
            *(float2*)&g_part[(size_t)r1 * 64 + col] =
                make_float2(acc[j][2], acc[j][3]);
    }
}

// x @ W0 -> hw = fp16(dis .* result). Needs dis (scan).
__global__ void __launch_bounds__(GNT) k_hmma_w0(
    const float* __restrict__ x,
    const float* __restrict__ W0,
    __half2* __restrict__ out, int n)
{
    __shared__ __half sA[128][PADH];
    __shared__ __half sB[64][PADH];
    int t = threadIdx.x;
    int lane = t & 31, warp = t >> 5;
    int rowBase = blockIdx.x * 128;
    float acc[8][4] = {};

    for (int i = 0; i < 2; i++) {
        load_A32g(sA, x, 128, i * 64, rowBase, n, t);
        load_Bg(sB, W0, i * 64, t);
        __syncthreads();
        hmma_tile8(sA, sB, warp, lane, acc);
        __syncthreads();
    }

    int r0 = rowBase + warp * 16 + (lane >> 2);
    int r1 = r0 + 8;
    float d0 = (r0 < n) ? g_dis[r0] : 0.f;
    float d1 = (r1 < n) ? g_dis[r1] : 0.f;
    #pragma unroll
    for (int j = 0; j < 8; j++) {
        int col = 8 * j + 2 * (lane & 3);
        if (r0 < n)
            out[(size_t)r0 * 32 + (col >> 1)] =
                __floats2half2_rn(acc[j][0] * d0, acc[j][1] * d0);
        if (r1 < n)
            out[(size_t)r1 * 32 + (col >> 1)] =
                __floats2half2_rn(acc[j][2] * d1, acc[j][3] * d1);
    }
}

// Layers 2,3 transform GEMM: out = fp16(dis .* (A16 @ W)), K=64
__global__ void __launch_bounds__(GNT) k_hmma_xform(
    const __half2* __restrict__ A16,
    const float* __restrict__ W,
    __half2* __restrict__ out, int n)
{
    __shared__ __half sA[128][PADH];
    __shared__ __half sB[64][PADH];
    int t = threadIdx.x;
    int lane = t & 31, warp = t >> 5;
    int rowBase = blockIdx.x * 128;
    float acc[8][4] = {};

    load_A16g(sA, A16, rowBase, n, t);
    load_Bg(sB, W, 0, t);
    __syncthreads();
    hmma_tile8(sA, sB, warp, lane, acc);
    __syncthreads();

    int r0 = rowBase + warp * 16 + (lane >> 2);
    int r1 = r0 + 8;
    float d0 = (r0 < n) ? g_dis[r0] : 0.f;
    float d1 = (r1 < n) ? g_dis[r1] : 0.f;
    #pragma unroll
    for (int j = 0; j < 8; j++) {
        int col = 8 * j + 2 * (lane & 3);
        if (r0 < n)
            out[(size_t)r0 * 32 + (col >> 1)] =
                __floats2half2_rn(acc[j][0] * d0, acc[j][1] * d0);
        if (r1 < n)
            out[(size_t)r1 * 32 + (col >> 1)] =
                __floats2half2_rn(acc[j][2] * d1, acc[j][3] * d1);
    }
}

// Final GEMM: out = partial + [h1|h2|h3] @ Wl[128:320] + bl   (K=192, fp16 A)
__global__ void __launch_bounds__(GNT) k_hmma_cat(
    const float* __restrict__ Wl,
    const float* __restrict__ bl,
    float* __restrict__ out, int n)
{
    __shared__ __half sA[128][PADH];
    __shared__ __half sB[64][PADH];
    int t = threadIdx.x;
    int lane = t & 31, warp = t >> 5;
    int rowBase = blockIdx.x * 128;
    float acc[8][4] = {};
    const float* Wl2 = Wl + 128 * 64;

    for (int i = 0; i < 3; i++) {
        const __half2* src = (i == 0) ? g_h1 : (i == 1) ? g_h2 : g_h3;
        load_A16g(sA, src, rowBase, n, t);
        load_Bg(sB, Wl2, i * 64, t);
        __syncthreads();
        hmma_tile8(sA, sB, warp, lane, acc);
        __syncthreads();
    }

    int r0 = rowBase + warp * 16 + (lane >> 2);
    int r1 = r0 + 8;
    #pragma unroll
    for (int j = 0; j < 8; j++) {
        int col = 8 * j + 2 * (lane & 3);
        float b0 = bl[col], b1 = bl[col + 1];
        if (r0 < n) {
            float2 p = *(const float2*)&g_part[(size_t)r0 * 64 + col];
            *(float2*)&out[(size_t)r0 * 64 + col] =
                make_float2(acc[j][0] + p.x + b0, acc[j][1] + p.y + b1);
        }
        if (r1 < n) {
            float2 p = *(const float2*)&g_part[(size_t)r1 * 64 + col];
            *(float2*)&out[(size_t)r1 * 64 + col] =
                make_float2(acc[j][2] + p.x + b0, acc[j][3] + p.y + b1);
        }
    }
}

// ===========================================================================
// Aggregation: warp per node, lane = one half2 (2 cols), unroll x8.
// Cols as int4 (2 LDG.128 per 8 edges); pure ADD inner op; dis[d] epilogue.
// ===========================================================================
__global__ void __launch_bounds__(256) k_gather(
    const __half2* __restrict__ hw,
    const float* __restrict__ bias,
    __half2* __restrict__ hout, int n)
{
    int g = blockIdx.x * blockDim.x + threadIdx.x;
    int node = g >> 5;
    int lane = g & 31;
    if (node >= n) return;
    int beg = g_rowptr[node];
    int end = g_rowptr[node + 1];
    float disd = g_dis[node];
    float a0 = 0.f, a1 = 0.f;
    int e = beg;
    while ((e & 3) && e < end) {
        int c = __ldg(&g_col[e]);
        float2 f = __half22float2(hw[(size_t)c * 32 + lane]);
        a0 += f.x; a1 += f.y;
        e++;
    }
    for (; e + 7 < end; e += 8) {
        int4 c0 = __ldg((const int4*)&g_col[e]);
        int4 c1 = __ldg((const int4*)&g_col[e + 4]);
        float2 f0 = __half22float2(hw[(size_t)c0.x * 32 + lane]);
        float2 f1 = __half22float2(hw[(size_t)c0.y * 32 + lane]);
        float2 f2 = __half22float2(hw[(size_t)c0.z * 32 + lane]);
        float2 f3 = __half22float2(hw[(size_t)c0.w * 32 + lane]);
        float2 f4 = __half22float2(hw[(size_t)c1.x * 32 + lane]);
        float2 f5 = __half22float2(hw[(size_t)c1.y * 32 + lane]);
        float2 f6 = __half22float2(hw[(size_t)c1.z * 32 + lane]);
        float2 f7 = __half22float2(hw[(size_t)c1.w * 32 + lane]);
        a0 += f0.x + f1.x + f2.x + f3.x;
        a1 += f0.y + f1.y + f2.y + f3.y;
        a0 += f4.x + f5.x + f6.x + f7.x;
        a1 += f4.y + f5.y + f6.y + f7.y;
    }
    for (; e < end; e++) {
        int c = __ldg(&g_col[e]);
        float2 f = __half22float2(hw[(size_t)c * 32 + lane]);
        a0 += f.x; a1 += f.y;
    }
    float b0 = bias[2 * lane], b1 = bias[2 * lane + 1];
    hout[(size_t)node * 32 + lane] =
        __floats2half2_rn(fmaxf(fmaf(disd, a0, b0), 0.f),
                          fmaxf(fmaf(disd, a1, b1), 0.f));
}

// ---------------------------------------------------------------------------
extern "C" void kernel_launch(void* const* d_in, const int* in_sizes, int n_in,
                              void* d_out, int out_size)
{
    const float* x  = (const float*)d_in[0];
    const int*   ei = (const int*)d_in[1];     // int32 edge_index [2, E]
    const float* W0 = (const float*)d_in[2];
    const float* b0 = (const float*)d_in[3];
    const float* W1 = (const float*)d_in[4];
    const float* b1 = (const float*)d_in[5];
    const float* W2 = (const float*)d_in[6];
    const float* b2 = (const float*)d_in[7];
    const float* Wl = (const float*)d_in[8];
    const float* bl = (const float*)d_in[9];
    float* out = (float*)d_out;

    int n = in_sizes[0] / 128;
    int e = in_sizes[1] / 2;
    int nb = (n + 1023) >> 10;

    __half2 *hw_ptr = nullptr, *h1_ptr = nullptr, *h2_ptr = nullptr, *h3_ptr = nullptr;
    cudaGetSymbolAddress((void**)&hw_ptr, g_hw);
    cudaGetSymbolAddress((void**)&h1_ptr, g_h1);
    cudaGetSymbolAddress((void**)&h2_ptr, g_h2);
    cudaGetSymbolAddress((void**)&h3_ptr, g_h3);

    int mma_blocks = (n + 127) / 128;
    int gather_blocks = (n * 32 + 255) / 256;

    cudaStream_t s2, s3;
    cudaStreamCreate(&s2);
    cudaStreamCreate(&s3);
    cudaEvent_t evRoot, evScan, evW0, evPart;
    cudaEventCreateWithFlags(&evRoot, cudaEventDisableTiming);
    cudaEventCreateWithFlags(&evScan, cudaEventDisableTiming);
    cudaEventCreateWithFlags(&evW0, cudaEventDisableTiming);
    cudaEventCreateWithFlags(&evPart, cudaEventDisableTiming);

    // fork s3 with a proper capture dependency, then run the dependency-free
    // partial GEMM at t=0 (joined only before the final cat GEMM)
    cudaEventRecord(evRoot, 0);
    cudaStreamWaitEvent(s3, evRoot, 0);
    k_hmma_part<<<mma_blocks, GNT, 0, s3>>>(x, Wl, n);
    cudaEventRecord(evPart, s3);

    // ---- CSR build (main stream) ----
    if ((e & 3) == 0) {
        int cth = e / 4;
        k_count4<<<(cth + 255) / 256, 256>>>(ei, e);
    } else {
        k_count1<<<(e + 255) / 256, 256>>>(ei, e);
    }
    k_scan_local<<<nb, 1024>>>(n);
    k_scan_add<<<nb, 1024>>>(nb, n);
    cudaEventRecord(evScan, 0);

    // W0 GEMM on s2 (needs dis; overlaps k_fill)
    cudaStreamWaitEvent(s2, evScan, 0);
    k_hmma_w0<<<mma_blocks, GNT, 0, s2>>>(x, W0, hw_ptr, n);
    cudaEventRecord(evW0, s2);

    k_fill<<<(e + n + 255) / 256, 256>>>(ei, e, n);

    // join: gather needs CSR fill + hw
    cudaStreamWaitEvent(0, evW0, 0);

    // ---- layer 1 aggregate ----
    k_gather<<<gather_blocks, 256>>>(hw_ptr, b0, h1_ptr, n);
    // ---- layer 2 ----
    k_hmma_xform<<<mma_blocks, GNT>>>(h1_ptr, W1, hw_ptr, n);
    k_gather<<<gather_blocks, 256>>>(hw_ptr, b1, h2_ptr, n);
    // ---- layer 3 ----
    k_hmma_xform<<<mma_blocks, GNT>>>(h2_ptr, W2, hw_ptr, n);
    k_gather<<<gather_blocks, 256>>>(hw_ptr, b2, h3_ptr, n);
    // ---- JK concat + linear (needs g_part) ----
    cudaStreamWaitEvent(0, evPart, 0);
    k_hmma_cat<<<mma_blocks, GNT>>>(Wl, bl, out, n);

    cudaEventDestroy(evRoot);
    cudaEventDestroy(evScan);
    cudaEventDestroy(evW0);
    cudaEventDestroy(evPart);
    cudaStreamDestroy(s2);
    cudaStreamDestroy(s3);
}